// round 15
// baseline (speedup 1.0000x reference)
#include <cuda_runtime.h>
#include <cstdint>

#define THREADS 256   // one query per thread, full candidate scan
#define BLK     16    // candidates per tracking block

// Packed-fp32x2 helper (sm_103a). Per-lane .rn rounding bit-identical to scalar.
#define FMA2(d, a, b, c) \
    asm("fma.rn.f32x2 %0, %1, %2, %3;" : "=l"(d) : "l"(a), "l"(b), "l"(c))

__device__ __forceinline__ unsigned long long pack2(float lo, float hi) {
    unsigned long long r;
    asm("mov.b64 %0, {%1, %2};" : "=l"(r) : "f"(lo), "f"(hi));
    return r;
}
__device__ __forceinline__ void unpack2(float& lo, float& hi,
                                        unsigned long long v) {
    asm("mov.b64 {%0, %1}, %2;" : "=f"(lo), "=f"(hi) : "l"(v));
}

// Track 3 smallest block-min values (B1<=B2<=B3) + block ids of the 2 smallest.
#define TRACK(bm, jj, B1, B2, B3, J1, J2)         \
    {                                             \
        bool lt1 = (bm) < B1;                     \
        bool lt2 = (bm) < B2;                     \
        B3 = lt2 ? B2 : fminf(B3, (bm));          \
        B2 = lt1 ? B1 : fminf(B2, (bm));          \
        J2 = lt1 ? J1 : (lt2 ? (jj) : J2);        \
        B1 = fminf(B1, (bm));                     \
        J1 = lt1 ? (jj) : J1;                     \
    }

// Exact evaluation: bit-matches the JAX reference rounding (tx = -2x
// prescaled; power-of-2 scaling commutes exactly with fp32 rounding):
//   cross2 = fma(tz,az, fma(ty,ay, tx*ax));  e = (sq + w) + cross2
// Lexicographic (e, idx) min -> first-occurrence argmin.
__device__ __forceinline__ void exact_scan(const float4* __restrict__ sh,
                                           int lo, int hi,
                                           float ax, float ay, float az,
                                           float sq, float& be, int& bi) {
    for (int j = lo; j < hi; j++) {
        int pp = j >> 1, lane = j & 1;
        float4 A  = sh[2 * pp];
        float4 Bv = sh[2 * pp + 1];
        float tx = lane ? A.y  : A.x;
        float ty = lane ? A.w  : A.z;
        float tz = lane ? Bv.y : Bv.x;
        float cw = lane ? Bv.w : Bv.z;
        float cr = fmaf(tz, az, fmaf(ty, ay, __fmul_rn(tx, ax)));
        float ek = __fadd_rn(__fadd_rn(sq, cw), cr);
        if (ek < be || (ek == be && j < bi)) { be = ek; bi = j; }
    }
}

// Chamfer distance, both directions fused via blockIdx.z.
// smem pair-SoA, pre-scaled by -2 on xyz:
//   sh2[2p]   = ((-2x0,-2x1),(-2y0,-2y1))
//   sh2[2p+1] = ((-2z0,-2z1),( w0,  w1))   w = |c|^2, reference rounding
//
// 256 threads (2 warps/SMSP — the high-issue-efficiency regime), ONE query
// per thread, full 8192-candidate scan, no cross-thread reduction.
// FAST key: f = fma(-2x,ax, fma(-2y,ay, fma(-2z,az, w)))  [3 FMA2 / 2 evals]
// tracked at 16-candidate blocks (3 smallest block mins + 2 block ids).
// EXACT repair: |f-(e-sq)| <= ~8 roundings << eps = 2e-5*sq+4e-5, so the
// exact argmin provably lies in block J1 (plus J2 if B2<=B1+eps); if even
// B3<=B1+eps (P~4e-4) the whole candidate set is rescanned exactly.
__global__ __launch_bounds__(THREADS, 1)
void chamfer_kernel(const float* __restrict__ xyz1,
                    const float* __restrict__ xyz2,
                    float* __restrict__ out,
                    int N, int M, int B) {
    extern __shared__ float4 sh[];

    const int dir = blockIdx.z;
    const int b   = blockIdx.y;

    const float* q;
    const float* c;
    int Nq, Nc;
    float* dist_out;
    float* idx_out;
    if (dir == 0) {
        q = xyz1; c = xyz2; Nq = N; Nc = M;
        dist_out = out;                                        // dist1
        idx_out  = out + (size_t)B * (N + M);                  // idx1
    } else {
        q = xyz2; c = xyz1; Nq = M; Nc = N;
        dist_out = out + (size_t)B * N;                        // dist2
        idx_out  = out + (size_t)B * (N + M) + (size_t)B * N;  // idx2
    }

    // ---- fill shared memory: (-2x,-2y,-2z, w), w with reference rounding ---
    const float* cb = c + (size_t)b * Nc * 3;
    const int npairs = Nc >> 1;
    for (int p = threadIdx.x; p < npairs; p += THREADS) {
        float x0 = cb[6 * p + 0], y0 = cb[6 * p + 1], z0 = cb[6 * p + 2];
        float x1 = cb[6 * p + 3], y1 = cb[6 * p + 4], z1 = cb[6 * p + 5];
        float w0 = __fadd_rn(__fadd_rn(__fmul_rn(x0, x0), __fmul_rn(y0, y0)),
                             __fmul_rn(z0, z0));
        float w1 = __fadd_rn(__fadd_rn(__fmul_rn(x1, x1), __fmul_rn(y1, y1)),
                             __fmul_rn(z1, z1));
        sh[2 * p]     = make_float4(-2.0f * x0, -2.0f * x1,
                                    -2.0f * y0, -2.0f * y1);
        sh[2 * p + 1] = make_float4(-2.0f * z0, -2.0f * z1, w0, w1);
    }
    __syncthreads();

    const ulonglong2* sh2 = reinterpret_cast<const ulonglong2*>(sh);

    // One query per thread, interleaved across CTAs for balance.
    const int i = threadIdx.x * gridDim.x + blockIdx.x;
    const bool valid = (i < Nq);
    const int iq = valid ? i : 0;

    const float* qp = q + ((size_t)b * Nq + iq) * 3;
    const float ax = qp[0], ay = qp[1], az = qp[2];
    const float sq = __fadd_rn(__fadd_rn(__fmul_rn(ax, ax), __fmul_rn(ay, ay)),
                               __fmul_rn(az, az));
    const unsigned long long AX = pack2(ax, ax);
    const unsigned long long AY = pack2(ay, ay);
    const unsigned long long AZ = pack2(az, az);

    const float INF = 3.402823466e38f;
    float b1 = INF, b2 = INF, b3 = INF;
    int   j1 = 0, j2 = 0;

    for (int j = 0; j < Nc; j += BLK) {
        float f[8];                        // pairwise mins (16 cands -> 8)
#pragma unroll
        for (int p = 0; p < 8; p++) {
            ulonglong2 A2 = sh2[j + 2 * p];      // (-2x pair),(-2y pair)
            ulonglong2 B2 = sh2[j + 2 * p + 1];  // (-2z pair),( w pair )
            unsigned long long u0, u1, u2;
            float lo, hi;
            FMA2(u0, B2.x, AZ, B2.y);            // fma(-2z,az, w)
            FMA2(u1, A2.y, AY, u0);              // fma(-2y,ay, .)
            FMA2(u2, A2.x, AX, u1);              // fma(-2x,ax, .)
            unpack2(lo, hi, u2);
            f[p] = fminf(lo, hi);
        }
        float m01 = fminf(f[0], f[1]), m23 = fminf(f[2], f[3]);
        float m45 = fminf(f[4], f[5]), m67 = fminf(f[6], f[7]);
        float bm  = fminf(fminf(m01, m23), fminf(m45, m67));
        TRACK(bm, j, b1, b2, b3, j1, j2);
    }

    // ---- exact repair over the certified candidate set ---------------------
    if (valid) {
        const float eps = fmaf(sq, 2e-5f, 4e-5f);
        float be = INF;
        int   bi = 0;
        if (b3 <= __fadd_rn(b1, eps)) {
            // extremely rare: 3+ blocks near-tied -> full exact rescan
            exact_scan(sh, 0, Nc, ax, ay, az, sq, be, bi);
        } else {
            exact_scan(sh, j1, j1 + BLK, ax, ay, az, sq, be, bi);
            if (b2 <= __fadd_rn(b1, eps))
                exact_scan(sh, j2, j2 + BLK, ax, ay, az, sq, be, bi);
        }
        dist_out[(size_t)b * Nq + i] = be;
        idx_out [(size_t)b * Nq + i] = (float)bi;
    }
}

extern "C" void kernel_launch(void* const* d_in, const int* in_sizes, int n_in,
                              void* d_out, int out_size) {
    const float* xyz1 = (const float*)d_in[0];
    const float* xyz2 = (const float*)d_in[1];
    float* out = (float*)d_out;

    const int B = 2;
    const int N = in_sizes[0] / (3 * B);
    const int M = in_sizes[1] / (3 * B);
    const int maxNM = (N > M) ? N : M;

    const size_t shmem = (size_t)maxNM * sizeof(float4);  // 128 KB for 8192
    cudaFuncSetAttribute(chamfer_kernel,
                         cudaFuncAttributeMaxDynamicSharedMemorySize,
                         (int)shmem);

    // 37 * 2 * 2 = 148 CTAs: one per SM, queries interleaved for balance.
    dim3 grid(37, B, 2);
    chamfer_kernel<<<grid, THREADS, shmem>>>(xyz1, xyz2, out, N, M, B);
}

// round 16
// speedup vs baseline: 1.2327x; 1.2327x over previous
#include <cuda_runtime.h>
#include <cstdint>

#define THREADS 256   // 128 query-pairs x 2 candidate-chunks (2 warps/SMSP)
#define NCHUNK  2
#define QPT     2     // queries per thread
#define BLK     16    // candidates per tracking block

// Packed-fp32x2 helper (sm_103a). Per-lane .rn rounding bit-identical to scalar.
#define FMA2(d, a, b, c) \
    asm("fma.rn.f32x2 %0, %1, %2, %3;" : "=l"(d) : "l"(a), "l"(b), "l"(c))

__device__ __forceinline__ unsigned long long pack2(float lo, float hi) {
    unsigned long long r;
    asm("mov.b64 %0, {%1, %2};" : "=l"(r) : "f"(lo), "f"(hi));
    return r;
}
__device__ __forceinline__ void unpack2(float& lo, float& hi,
                                        unsigned long long v) {
    asm("mov.b64 {%0, %1}, %2;" : "=f"(lo), "=f"(hi) : "l"(v));
}

// Track 3 smallest block-min values (B1<=B2<=B3) + block ids of the 2 smallest.
#define TRACK(bm, jj, B1, B2, B3, J1, J2)         \
    {                                             \
        bool lt1 = (bm) < B1;                     \
        bool lt2 = (bm) < B2;                     \
        B3 = lt2 ? B2 : fminf(B3, (bm));          \
        B2 = lt1 ? B1 : fminf(B2, (bm));          \
        J2 = lt1 ? J1 : (lt2 ? (jj) : J2);        \
        B1 = fminf(B1, (bm));                     \
        J1 = lt1 ? (jj) : J1;                     \
    }

// Exact evaluation: bit-matches the JAX reference rounding (tx = -2x
// prescaled; power-of-2 scaling commutes exactly with fp32 rounding):
//   cross2 = fma(tz,az, fma(ty,ay, tx*ax));  e = (sq + w) + cross2
// Lexicographic (e, idx) min -> first-occurrence argmin.
__device__ __forceinline__ void exact_scan(const float4* __restrict__ sh,
                                           int lo, int hi,
                                           float ax, float ay, float az,
                                           float sq, float& be, int& bi) {
    for (int j = lo; j < hi; j++) {
        int pp = j >> 1, lane = j & 1;
        float4 A  = sh[2 * pp];
        float4 Bv = sh[2 * pp + 1];
        float tx = lane ? A.y  : A.x;
        float ty = lane ? A.w  : A.z;
        float tz = lane ? Bv.y : Bv.x;
        float cw = lane ? Bv.w : Bv.z;
        float cr = fmaf(tz, az, fmaf(ty, ay, __fmul_rn(tx, ax)));
        float ek = __fadd_rn(__fadd_rn(sq, cw), cr);
        if (ek < be || (ek == be && j < bi)) { be = ek; bi = j; }
    }
}

// Chamfer distance, both directions fused via blockIdx.z.
// smem pair-SoA, pre-scaled by -2 on xyz:
//   sh2[2p]   = ((-2x0,-2x1),(-2y0,-2y1))
//   sh2[2p+1] = ((-2z0,-2z1),( w0,  w1))   w = |c|^2, reference rounding
//
// 256 threads = 2 warps/SMSP (the high-issue-efficiency regime from R2/R3),
// TWO queries per thread (each LDS.128 amortized over 4 evals), each thread
// scans one 4096-candidate half; 2-chunk merge through 4KB static smem.
// FAST key: f = fma(-2x,ax, fma(-2y,ay, fma(-2z,az, w)))  [3 FMA2 / 2 evals]
// tracked at 16-candidate blocks (3 smallest block mins + 2 block ids).
// EXACT repair: |f-(e-sq)| <= ~8 roundings << eps = 2e-5*sq+4e-5, so the
// exact argmin provably lies in block J1 (plus J2 if B2<=B1+eps); if even
// B3<=B1+eps (P~4e-4) the whole half-chunk is rescanned exactly.
__global__ __launch_bounds__(THREADS, 1)
void chamfer_kernel(const float* __restrict__ xyz1,
                    const float* __restrict__ xyz2,
                    float* __restrict__ out,
                    int N, int M, int B) {
    extern __shared__ float4 sh[];
    __shared__ float2 red[QPT][THREADS];   // per-query-slot (best, idx)

    const int dir = blockIdx.z;
    const int b   = blockIdx.y;

    const float* q;
    const float* c;
    int Nq, Nc;
    float* dist_out;
    float* idx_out;
    if (dir == 0) {
        q = xyz1; c = xyz2; Nq = N; Nc = M;
        dist_out = out;                                        // dist1
        idx_out  = out + (size_t)B * (N + M);                  // idx1
    } else {
        q = xyz2; c = xyz1; Nq = M; Nc = N;
        dist_out = out + (size_t)B * N;                        // dist2
        idx_out  = out + (size_t)B * (N + M) + (size_t)B * N;  // idx2
    }

    // ---- fill shared memory: (-2x,-2y,-2z, w), w with reference rounding ---
    const float* cb = c + (size_t)b * Nc * 3;
    const int npairs = Nc >> 1;
    for (int p = threadIdx.x; p < npairs; p += THREADS) {
        float x0 = cb[6 * p + 0], y0 = cb[6 * p + 1], z0 = cb[6 * p + 2];
        float x1 = cb[6 * p + 3], y1 = cb[6 * p + 4], z1 = cb[6 * p + 5];
        float w0 = __fadd_rn(__fadd_rn(__fmul_rn(x0, x0), __fmul_rn(y0, y0)),
                             __fmul_rn(z0, z0));
        float w1 = __fadd_rn(__fadd_rn(__fmul_rn(x1, x1), __fmul_rn(y1, y1)),
                             __fmul_rn(z1, z1));
        sh[2 * p]     = make_float4(-2.0f * x0, -2.0f * x1,
                                    -2.0f * y0, -2.0f * y1);
        sh[2 * p + 1] = make_float4(-2.0f * z0, -2.0f * z1, w0, w1);
    }
    __syncthreads();

    const ulonglong2* sh2 = reinterpret_cast<const ulonglong2*>(sh);

    const int qp    = threadIdx.x & 127;   // query pair (0..127)
    const int chunk = threadIdx.x >> 7;    // candidate chunk (0..1)

    float ax0, ay0, az0, sq0, ax1, ay1, az1, sq1;
    {
        const int i0 = (QPT * qp + 0) * gridDim.x + blockIdx.x;
        const int i1 = (QPT * qp + 1) * gridDim.x + blockIdx.x;
        const float* p0 = q + ((size_t)b * Nq + ((i0 < Nq) ? i0 : 0)) * 3;
        const float* p1 = q + ((size_t)b * Nq + ((i1 < Nq) ? i1 : 0)) * 3;
        ax0 = p0[0]; ay0 = p0[1]; az0 = p0[2];
        ax1 = p1[0]; ay1 = p1[1]; az1 = p1[2];
        sq0 = __fadd_rn(__fadd_rn(__fmul_rn(ax0, ax0), __fmul_rn(ay0, ay0)),
                        __fmul_rn(az0, az0));
        sq1 = __fadd_rn(__fadd_rn(__fmul_rn(ax1, ax1), __fmul_rn(ay1, ay1)),
                        __fmul_rn(az1, az1));
    }
    const unsigned long long AX0 = pack2(ax0, ax0), AY0 = pack2(ay0, ay0);
    const unsigned long long AZ0 = pack2(az0, az0);
    const unsigned long long AX1 = pack2(ax1, ax1), AY1 = pack2(ay1, ay1);
    const unsigned long long AZ1 = pack2(az1, az1);

    const int csz   = Nc / NCHUNK;         // 4096
    const int cbase = chunk * csz;

    const float INF = 3.402823466e38f;
    float b1q0 = INF, b2q0 = INF, b3q0 = INF;
    float b1q1 = INF, b2q1 = INF, b3q1 = INF;
    int   j1q0 = cbase, j2q0 = cbase, j1q1 = cbase, j2q1 = cbase;

    for (int j = cbase; j < cbase + csz; j += BLK) {
        float f0[8], f1[8];                // pairwise mins (16 cands -> 8)
#pragma unroll
        for (int p = 0; p < 8; p++) {
            ulonglong2 A2 = sh2[j + 2 * p];      // (-2x pair),(-2y pair)
            ulonglong2 B2 = sh2[j + 2 * p + 1];  // (-2z pair),( w pair )
            unsigned long long u0, u1, u2;
            float lo, hi;
            FMA2(u0, B2.x, AZ0, B2.y);
            FMA2(u1, A2.y, AY0, u0);
            FMA2(u2, A2.x, AX0, u1);
            unpack2(lo, hi, u2);
            f0[p] = fminf(lo, hi);
            FMA2(u0, B2.x, AZ1, B2.y);
            FMA2(u1, A2.y, AY1, u0);
            FMA2(u2, A2.x, AX1, u1);
            unpack2(lo, hi, u2);
            f1[p] = fminf(lo, hi);
        }
        float a01 = fminf(f0[0], f0[1]), a23 = fminf(f0[2], f0[3]);
        float a45 = fminf(f0[4], f0[5]), a67 = fminf(f0[6], f0[7]);
        float bm0 = fminf(fminf(a01, a23), fminf(a45, a67));
        float c01 = fminf(f1[0], f1[1]), c23 = fminf(f1[2], f1[3]);
        float c45 = fminf(f1[4], f1[5]), c67 = fminf(f1[6], f1[7]);
        float bm1 = fminf(fminf(c01, c23), fminf(c45, c67));
        TRACK(bm0, j, b1q0, b2q0, b3q0, j1q0, j2q0);
        TRACK(bm1, j, b1q1, b2q1, b3q1, j1q1, j2q1);
    }

    // ---- exact repair over the certified candidate set ---------------------
    {
        float eps = fmaf(sq0, 2e-5f, 4e-5f);
        float be = INF; int bi = 0;
        if (b3q0 <= __fadd_rn(b1q0, eps)) {
            exact_scan(sh, cbase, cbase + csz, ax0, ay0, az0, sq0, be, bi);
        } else {
            exact_scan(sh, j1q0, j1q0 + BLK, ax0, ay0, az0, sq0, be, bi);
            if (b2q0 <= __fadd_rn(b1q0, eps))
                exact_scan(sh, j2q0, j2q0 + BLK, ax0, ay0, az0, sq0, be, bi);
        }
        red[0][threadIdx.x] = make_float2(be, (float)bi);
    }
    {
        float eps = fmaf(sq1, 2e-5f, 4e-5f);
        float be = INF; int bi = 0;
        if (b3q1 <= __fadd_rn(b1q1, eps)) {
            exact_scan(sh, cbase, cbase + csz, ax1, ay1, az1, sq1, be, bi);
        } else {
            exact_scan(sh, j1q1, j1q1 + BLK, ax1, ay1, az1, sq1, be, bi);
            if (b2q1 <= __fadd_rn(b1q1, eps))
                exact_scan(sh, j2q1, j2q1 + BLK, ax1, ay1, az1, sq1, be, bi);
        }
        red[1][threadIdx.x] = make_float2(be, (float)bi);
    }
    __syncthreads();

    // ---- merge the 2 chunks; chunk 0 first + strict < keeps the smaller
    //      candidate index on exact ties (first-occurrence argmin) ---------
    if (threadIdx.x < 256) {
        const int l  = threadIdx.x;        // query lane 0..255
        const int qi = l * gridDim.x + blockIdx.x;
        if (qi < Nq) {
            const int ql = l & 1;          // query slot within pair
            const int pp = l >> 1;         // pair id
            float2 r  = red[ql][pp];       // chunk 0
            float2 rc = red[ql][128 + pp]; // chunk 1
            if (rc.x < r.x) r = rc;
            dist_out[(size_t)b * Nq + qi] = r.x;
            idx_out [(size_t)b * Nq + qi] = r.y;
        }
    }
}

extern "C" void kernel_launch(void* const* d_in, const int* in_sizes, int n_in,
                              void* d_out, int out_size) {
    const float* xyz1 = (const float*)d_in[0];
    const float* xyz2 = (const float*)d_in[1];
    float* out = (float*)d_out;

    const int B = 2;
    const int N = in_sizes[0] / (3 * B);
    const int M = in_sizes[1] / (3 * B);
    const int maxNM = (N > M) ? N : M;

    const size_t shmem = (size_t)maxNM * sizeof(float4);  // 128 KB for 8192
    cudaFuncSetAttribute(chamfer_kernel,
                         cudaFuncAttributeMaxDynamicSharedMemorySize,
                         (int)shmem);

    // 37 * 2 * 2 = 148 CTAs: one per SM, queries interleaved for balance.
    dim3 grid(37, B, 2);
    chamfer_kernel<<<grid, THREADS, shmem>>>(xyz1, xyz2, out, N, M, B);
}